// round 12
// baseline (speedup 1.0000x reference)
#include <cuda_runtime.h>
#include <cuda_bf16.h>
#include <math.h>
#include <stdint.h>

// Problem constants
#define BB 2
#define SS 2048
#define DD 1024
#define HH 16
#define HDIM 64
#define MM (BB*SS)          // 4096 total rows
#define NQT 16              // q tiles of 128 per (b,h)

// ---------------------------------------------------------------------------
// Scratch (device globals — no allocations allowed)
// ---------------------------------------------------------------------------
__device__ float g_q [MM*DD];
__device__ float g_k [MM*DD];
__device__ float g_v [MM*DD];
__device__ __nv_bfloat16 g_xh [MM*DD];
__device__ __nv_bfloat16 g_xl [MM*DD];
__device__ __nv_bfloat16 g_aoh[MM*DD];
__device__ __nv_bfloat16 g_aol[MM*DD];
__device__ __nv_bfloat16 g_wth[4][DD*DD];
__device__ __nv_bfloat16 g_wtl[4][DD*DD];
// flash operands (post-RoPE, bf16x3 split)
__device__ __nv_bfloat16 g_qh [MM*DD];
__device__ __nv_bfloat16 g_ql [MM*DD];
__device__ __nv_bfloat16 g_kh [MM*DD];
__device__ __nv_bfloat16 g_kl [MM*DD];
__device__ __nv_bfloat16 g_vth[BB*HH*HDIM*SS];  // [bh][d][s]
__device__ __nv_bfloat16 g_vtl[BB*HH*HDIM*SS];

// ---------------------------------------------------------------------------
// PTX helpers (sm_80-class only — valid for compute_103 w/o 'a' suffix)
// ---------------------------------------------------------------------------
__device__ __forceinline__ uint32_t smem_u32(const void* p) {
    uint32_t a;
    asm("{ .reg .u64 t; cvta.to.shared.u64 t, %1; cvt.u32.u64 %0, t; }"
        : "=r"(a) : "l"(p));
    return a;
}

#define LDSM4(R0, R1, R2, R3, addr) \
    asm volatile("ldmatrix.sync.aligned.m8n8.x4.shared.b16 {%0,%1,%2,%3}, [%4];" \
                 : "=r"(R0), "=r"(R1), "=r"(R2), "=r"(R3) : "r"(addr))

#define MMA16816(d, a, b) \
    asm volatile("mma.sync.aligned.m16n8k16.row.col.f32.bf16.bf16.f32 " \
                 "{%0,%1,%2,%3}, {%4,%5,%6,%7}, {%8,%9}, {%0,%1,%2,%3};" \
                 : "+f"((d)[0]), "+f"((d)[1]), "+f"((d)[2]), "+f"((d)[3]) \
                 : "r"((a)[0]), "r"((a)[1]), "r"((a)[2]), "r"((a)[3]), \
                   "r"((b)[0]), "r"((b)[1]))

#define CP_ASYNC16(s, g) \
    asm volatile("cp.async.cg.shared.global [%0], [%1], 16;" :: "r"(s), "l"(g))
#define CP_COMMIT() asm volatile("cp.async.commit_group;" ::: "memory")
#define CP_WAIT1()  asm volatile("cp.async.wait_group 1;" ::: "memory")
#define CP_WAIT0()  asm volatile("cp.async.wait_group 0;" ::: "memory")

__device__ __forceinline__ void split_pack2(float x, float y,
                                            uint32_t& hi, uint32_t& lo) {
    __nv_bfloat16 hx = __float2bfloat16(x), hy = __float2bfloat16(y);
    __nv_bfloat16 lx = __float2bfloat16(x - __bfloat162float(hx));
    __nv_bfloat16 ly = __float2bfloat16(y - __bfloat162float(hy));
    hi = (uint32_t)__bfloat16_as_ushort(hx) | ((uint32_t)__bfloat16_as_ushort(hy) << 16);
    lo = (uint32_t)__bfloat16_as_ushort(lx) | ((uint32_t)__bfloat16_as_ushort(ly) << 16);
}

// ---------------------------------------------------------------------------
// prep_kernel: fused {transpose_split4 (blocks 0..4095)} ∪ {split_f32 x
// (blocks 4096..8191)}. Independent workloads, one launch.
// ---------------------------------------------------------------------------
__global__ __launch_bounds__(256) void prep_kernel(const float* __restrict__ x,
                                                   const float* __restrict__ W0,
                                                   const float* __restrict__ W1,
                                                   const float* __restrict__ W2,
                                                   const float* __restrict__ W3) {
    __shared__ float t[32][33];
    const int bx = blockIdx.x;
    const int tid = threadIdx.x;
    if (bx < 4096) {
        // transpose+split weights: decompose bx -> (n0:32, k0:32, w:4)
        const int w  = bx >> 10;
        const int rem = bx & 1023;
        const int n0 = (rem & 31) * 32;
        const int k0 = (rem >> 5) * 32;
        const float* W = (w == 0) ? W0 : (w == 1) ? W1 : (w == 2) ? W2 : W3;
        __nv_bfloat16* th = g_wth[w];
        __nv_bfloat16* tl = g_wtl[w];
        const int tx = tid & 31, ty = tid >> 5;   // 32 x 8
        #pragma unroll
        for (int r = 0; r < 4; r++)
            t[ty + 8 * r][tx] = W[(size_t)(k0 + ty + 8 * r) * DD + n0 + tx];
        __syncthreads();
        #pragma unroll
        for (int r = 0; r < 4; r++) {
            float v = t[tx][ty + 8 * r];
            __nv_bfloat16 h = __float2bfloat16(v);
            __nv_bfloat16 l = __float2bfloat16(v - __bfloat162float(h));
            size_t idx = (size_t)(n0 + ty + 8 * r) * DD + k0 + tx;
            th[idx] = h;
            tl[idx] = l;
        }
    } else {
        // split x -> xh/xl (1 float4 per thread)
        const int i = (bx - 4096) * 256 + tid;    // < MM*DD/4
        float4 v = ((const float4*)x)[i];
        float vv[4] = {v.x, v.y, v.z, v.w};
        __nv_bfloat16 h[4], l[4];
        #pragma unroll
        for (int j = 0; j < 4; j++) {
            h[j] = __float2bfloat16(vv[j]);
            l[j] = __float2bfloat16(vv[j] - __bfloat162float(h[j]));
        }
        ((__nv_bfloat162*)g_xh)[2 * i + 0] = __nv_bfloat162(h[0], h[1]);
        ((__nv_bfloat162*)g_xh)[2 * i + 1] = __nv_bfloat162(h[2], h[3]);
        ((__nv_bfloat162*)g_xl)[2 * i + 0] = __nv_bfloat162(l[0], l[1]);
        ((__nv_bfloat162*)g_xl)[2 * i + 1] = __nv_bfloat162(l[2], l[3]);
    }
}

// ---------------------------------------------------------------------------
// mid_kernel: fused {rope_split (blocks 0..8191)} ∪ {vtrans_split
// (blocks 8192..12287)}. Both depend only on gemm_qkv outputs.
// ---------------------------------------------------------------------------
__global__ __launch_bounds__(256) void mid_kernel() {
    __shared__ float t[32][33];
    const int bx = blockIdx.x;
    const int tid = threadIdx.x;
    if (bx < 8192) {
        // RoPE + split Q/K
        int idx = bx * 256 + tid;
        int j = idx & 31;
        int h = (idx >> 5) & (HH - 1);
        int m = idx >> 9;
        int pos = m & (SS - 1);

        float freq = expf(-(float)j * (9.210340371976184f / 32.0f));
        float sn, cs;
        sincosf((float)pos * freq, &sn, &cs);

        int base = m * DD + h * HDIM;
        float q1 = g_q[base + j], q2 = g_q[base + j + 32];
        float k1 = g_k[base + j], k2 = g_k[base + j + 32];
        float qa = q1 * cs - q2 * sn;
        float qb = q2 * cs + q1 * sn;
        float ka = k1 * cs - k2 * sn;
        float kb = k2 * cs + k1 * sn;

        __nv_bfloat16 tt;
        tt = __float2bfloat16(qa); g_qh[base + j] = tt;
        g_ql[base + j] = __float2bfloat16(qa - __bfloat162float(tt));
        tt = __float2bfloat16(qb); g_qh[base + j + 32] = tt;
        g_ql[base + j + 32] = __float2bfloat16(qb - __bfloat162float(tt));
        tt = __float2bfloat16(ka); g_kh[base + j] = tt;
        g_kl[base + j] = __float2bfloat16(ka - __bfloat162float(tt));
        tt = __float2bfloat16(kb); g_kh[base + j + 32] = tt;
        g_kl[base + j + 32] = __float2bfloat16(kb - __bfloat162float(tt));
    } else {
        // V transpose+split: decompose (bx-8192) -> (x:64, y:2, z:32)
        const int b2 = bx - 8192;
        const int s0 = (b2 & 63) * 32;
        const int d0 = ((b2 >> 6) & 1) * 32;
        const int bh = b2 >> 7;
        const int b = bh >> 4, h = bh & 15;
        const int tx = tid & 31, ty = tid >> 5;   // 32 x 8
        #pragma unroll
        for (int r = 0; r < 4; r++)
            t[ty + 8 * r][tx] = g_v[(size_t)(b * SS + s0 + ty + 8 * r) * DD + h * HDIM + d0 + tx];
        __syncthreads();
        #pragma unroll
        for (int r = 0; r < 4; r++) {
            float v = t[tx][ty + 8 * r];
            __nv_bfloat16 hi = __float2bfloat16(v);
            __nv_bfloat16 lo = __float2bfloat16(v - __bfloat162float(hi));
            size_t idx = ((size_t)bh * HDIM + d0 + ty + 8 * r) * SS + s0 + tx;
            g_vth[idx] = hi;
            g_vtl[idx] = lo;
        }
    }
}

// ---------------------------------------------------------------------------
// bf16x3 HMMA GEMM (proven R6/R9 core): C = (Ah+Al)*(Bh+Bl)^T, 3 MMA terms.
// ---------------------------------------------------------------------------
#define PA 80
#define ARR_BYTES (128 * PA)
#define STAGE_BYTES (4 * ARR_BYTES)
#define SMEM_GEMM (2 * STAGE_BYTES)

__device__ __forceinline__ void gemm_body(const __nv_bfloat16* __restrict__ Ah,
                                          const __nv_bfloat16* __restrict__ Al,
                                          const __nv_bfloat16* __restrict__ Bh,
                                          const __nv_bfloat16* __restrict__ Bl,
                                          float* __restrict__ C,
                                          int rowBase, int colBase,
                                          char* smem) {
    const int tid = threadIdx.x;
    const int lane = tid & 31;
    const int wid = tid >> 5;
    const int wm = wid >> 2;
    const int wn = wid & 3;
    const uint32_t sb = smem_u32(smem);

    const int lr = tid >> 2;
    const int lc = tid & 3;

    float acc[4][4][4];
    #pragma unroll
    for (int i = 0; i < 4; i++)
        #pragma unroll
        for (int j = 0; j < 4; j++)
            #pragma unroll
            for (int r = 0; r < 4; r++) acc[i][j][r] = 0.f;

    const int a_r = (lane & 15);
    const int a_c = (lane >> 4);
    const int b_r = (lane & 7) + ((lane >> 4) << 3);
    const int b_c = (lane >> 3) & 1;

    auto load_stage = [&](int kb, int stage) {
        const uint32_t s0 = sb + stage * STAGE_BYTES;
        const int kOff = kb * 32 + lc * 8;
        #pragma unroll
        for (int half = 0; half < 2; half++) {
            const int r = lr + half * 64;
            const uint32_t sa = s0 + r * PA + lc * 16;
            const size_t gA = (size_t)(rowBase + r) * DD + kOff;
            const size_t gB = (size_t)(colBase + r) * DD + kOff;
            CP_ASYNC16(sa + 0 * ARR_BYTES, Ah + gA);
            CP_ASYNC16(sa + 1 * ARR_BYTES, Al + gA);
            CP_ASYNC16(sa + 2 * ARR_BYTES, Bh + gB);
            CP_ASYNC16(sa + 3 * ARR_BYTES, Bl + gB);
        }
        CP_COMMIT();
    };

    load_stage(0, 0);

    for (int kb = 0; kb < 32; kb++) {
        if (kb + 1 < 32) {
            load_stage(kb + 1, (kb + 1) & 1);
            CP_WAIT1();
        } else {
            CP_WAIT0();
        }
        __syncthreads();

        const uint32_t s0 = sb + (kb & 1) * STAGE_BYTES;
        const uint32_t sAh = s0 + 0 * ARR_BYTES;
        const uint32_t sAl = s0 + 1 * ARR_BYTES;
        const uint32_t sBh = s0 + 2 * ARR_BYTES;
        const uint32_t sBl = s0 + 3 * ARR_BYTES;

        #pragma unroll
        for (int ks = 0; ks < 2; ks++) {
            uint32_t ah[4][4], al[4][4], bh[4][2], bl[4][2];
            const int kc0 = ks * 2;
            #pragma unroll
            for (int ma = 0; ma < 4; ma++) {
                const int row = wm * 64 + ma * 16 + a_r;
                const uint32_t addr = row * PA + (kc0 + a_c) * 16;
                LDSM4(ah[ma][0], ah[ma][1], ah[ma][2], ah[ma][3], sAh + addr);
                LDSM4(al[ma][0], al[ma][1], al[ma][2], al[ma][3], sAl + addr);
            }
            #pragma unroll
            for (int nb = 0; nb < 2; nb++) {
                const int row = wn * 32 + nb * 16 + b_r;
                const uint32_t addr = row * PA + (kc0 + b_c) * 16;
                uint32_t t0, t1, t2, t3;
                LDSM4(t0, t1, t2, t3, sBh + addr);
                bh[2 * nb][0] = t0; bh[2 * nb][1] = t1;
                bh[2 * nb + 1][0] = t2; bh[2 * nb + 1][1] = t3;
                LDSM4(t0, t1, t2, t3, sBl + addr);
                bl[2 * nb][0] = t0; bl[2 * nb][1] = t1;
                bl[2 * nb + 1][0] = t2; bl[2 * nb + 1][1] = t3;
            }
            #pragma unroll
            for (int ma = 0; ma < 4; ma++)
                #pragma unroll
                for (int na = 0; na < 4; na++) {
                    MMA16816(acc[ma][na], ah[ma], bh[na]);
                    MMA16816(acc[ma][na], ah[ma], bl[na]);
                    MMA16816(acc[ma][na], al[ma], bh[na]);
                }
        }
        __syncthreads();
    }

    const int er = lane >> 2;
    const int ec = (lane & 3) * 2;
    #pragma unroll
    for (int ma = 0; ma < 4; ma++) {
        const int row0 = rowBase + wm * 64 + ma * 16 + er;
        #pragma unroll
        for (int na = 0; na < 4; na++) {
            const int col = colBase + wn * 32 + na * 8 + ec;
            *(float2*)&C[(size_t)row0 * DD + col] =
                make_float2(acc[ma][na][0], acc[ma][na][1]);
            *(float2*)&C[(size_t)(row0 + 8) * DD + col] =
                make_float2(acc[ma][na][2], acc[ma][na][3]);
        }
    }
}

__global__ __launch_bounds__(256) void gemm_qkv(const __nv_bfloat16* __restrict__ xh,
                                                const __nv_bfloat16* __restrict__ xl,
                                                const __nv_bfloat16* __restrict__ wth,
                                                const __nv_bfloat16* __restrict__ wtl) {
    extern __shared__ char smem[];
    const int gw = blockIdx.x >> 3;
    const int colBase = (blockIdx.x & 7) * 128;
    const int rowBase = blockIdx.y * 128;
    float* C = (gw == 0) ? g_q : (gw == 1) ? g_k : g_v;
    const __nv_bfloat16* Bh = wth + (size_t)gw * DD * DD;
    const __nv_bfloat16* Bl = wtl + (size_t)gw * DD * DD;
    gemm_body(xh, xl, Bh, Bl, C, rowBase, colBase, smem);
}

__global__ __launch_bounds__(256) void gemm_one(const __nv_bfloat16* __restrict__ Ah,
                                                const __nv_bfloat16* __restrict__ Al,
                                                const __nv_bfloat16* __restrict__ Bh,
                                                const __nv_bfloat16* __restrict__ Bl,
                                                float* __restrict__ C) {
    extern __shared__ char smem[];
    gemm_body(Ah, Al, Bh, Bl, C, blockIdx.y * 128, blockIdx.x * 128, smem);
}

// ---------------------------------------------------------------------------
// Tensor-core causal flash attention (bf16x3, proven R6/R9/R11 core).
// Epilogue writes split bf16 aoh/aol directly.
// ---------------------------------------------------------------------------
#define FSTR 144
#define QAREA (128 * FSTR)
#define KVARR (64 * FSTR)
#define KVSTAGE (4 * KVARR)
#define SMEM_FLASH (2 * KVSTAGE)

__global__ __launch_bounds__(256, 1) void flash_tc() {
    extern __shared__ char smc[];
    const uint32_t sb = smem_u32(smc);
    const int tid = threadIdx.x, lane = tid & 31, warp = tid >> 5;
    const int qt = (NQT - 1) - blockIdx.x;
    const int bh = blockIdx.y;
    const int b = bh >> 4, h = bh & 15;
    const int qbase = qt * 128;
    const size_t mbase = (size_t)b * SS;

    {
        const int r = tid >> 1;
        const int c0 = (tid & 1) * 4;
        const size_t g = (mbase + qbase + r) * DD + (size_t)h * HDIM;
        #pragma unroll
        for (int it = 0; it < 4; it++) {
            int c = c0 + it;
            CP_ASYNC16(sb + r * FSTR + c * 16, g_qh + g + c * 8);
            CP_ASYNC16(sb + QAREA + r * FSTR + c * 16, g_ql + g + c * 8);
        }
        CP_COMMIT();
    }
    CP_WAIT0();
    __syncthreads();

    uint32_t qf[2][4][4];
    {
        const int a_r = lane & 15, a_c = lane >> 4;
        #pragma unroll
        for (int ks = 0; ks < 4; ks++) {
            uint32_t addr = sb + (warp * 16 + a_r) * FSTR + (ks * 2 + a_c) * 16;
            LDSM4(qf[0][ks][0], qf[0][ks][1], qf[0][ks][2], qf[0][ks][3], addr);
            LDSM4(qf[1][ks][0], qf[1][ks][1], qf[1][ks][2], qf[1][ks][3], addr + QAREA);
        }
    }
    __syncthreads();

    float mi[2] = {-3.0e38f, -3.0e38f};
    float li[2] = {0.f, 0.f};
    float oacc[8][4];
    #pragma unroll
    for (int i = 0; i < 8; i++)
        #pragma unroll
        for (int j = 0; j < 4; j++) oacc[i][j] = 0.f;

    auto load_kv = [&](int kt, int stage) {
        const uint32_t s0 = sb + stage * KVSTAGE;
        const int r = tid >> 2;
        const int cb = tid & 3;
        const size_t gk = (mbase + kt * 64 + r) * DD + (size_t)h * HDIM;
        const size_t gv = ((size_t)bh * HDIM + r) * SS + kt * 64;
        #pragma unroll
        for (int cc = 0; cc < 2; cc++) {
            const int c = cb + cc * 4;
            const uint32_t sa = s0 + r * FSTR + c * 16;
            CP_ASYNC16(sa + 0 * KVARR, g_kh + gk + c * 8);
            CP_ASYNC16(sa + 1 * KVARR, g_kl + gk + c * 8);
            CP_ASYNC16(sa + 2 * KVARR, g_vth + gv + c * 8);
            CP_ASYNC16(sa + 3 * KVARR, g_vtl + gv + c * 8);
        }
        CP_COMMIT();
    };

    const int nt = 2 * qt + 2;
    load_kv(0, 0);

    const int b_r = (lane & 7) + ((lane >> 4) << 3);
    const int b_c = (lane >> 3) & 1;
    const int r0loc = warp * 16 + (lane >> 2);
    const float scale = 0.125f;

    for (int kt = 0; kt < nt; kt++) {
        CP_WAIT0();
        __syncthreads();
        if (kt + 1 < nt) load_kv(kt + 1, (kt + 1) & 1);

        const uint32_t s0 = sb + (kt & 1) * KVSTAGE;

        float sacc[8][4];
        #pragma unroll
        for (int i = 0; i < 8; i++)
            #pragma unroll
            for (int j = 0; j < 4; j++) sacc[i][j] = 0.f;

        #pragma unroll
        for (int ks = 0; ks < 4; ks++) {
            uint32_t kfh[8][2], kfl[8][2];
            #pragma unroll
            for (int nb = 0; nb < 4; nb++) {
                uint32_t addr = s0 + (nb * 16 + b_r) * FSTR + (ks * 2 + b_c) * 16;
                uint32_t t0, t1, t2, t3;
                LDSM4(t0, t1, t2, t3, addr);
                kfh[2 * nb][0] = t0; kfh[2 * nb][1] = t1;
                kfh[2 * nb + 1][0] = t2; kfh[2 * nb + 1][1] = t3;
                LDSM4(t0, t1, t2, t3, addr + KVARR);
                kfl[2 * nb][0] = t0; kfl[2 * nb][1] = t1;
                kfl[2 * nb + 1][0] = t2; kfl[2 * nb + 1][1] = t3;
            }
            #pragma unroll
            for (int nb = 0; nb < 8; nb++) {
                MMA16816(sacc[nb], qf[0][ks], kfh[nb]);
                MMA16816(sacc[nb], qf[0][ks], kfl[nb]);
                MMA16816(sacc[nb], qf[1][ks], kfh[nb]);
            }
        }

        const bool diag = (kt >= 2 * qt);
        #pragma unroll
        for (int nb = 0; nb < 8; nb++)
            #pragma unroll
            for (int e = 0; e < 4; e++) {
                float s = sacc[nb][e] * scale;
                if (diag) {
                    int row = qbase + r0loc + ((e >= 2) ? 8 : 0);
                    int col = kt * 64 + nb * 8 + (lane & 3) * 2 + (e & 1);
                    if (col > row) s = -3.0e38f;
                }
                sacc[nb][e] = s;
            }

        float rm[2] = {-3.0e38f, -3.0e38f};
        #pragma unroll
        for (int nb = 0; nb < 8; nb++) {
            rm[0] = fmaxf(rm[0], fmaxf(sacc[nb][0], sacc[nb][1]));
            rm[1] = fmaxf(rm[1], fmaxf(sacc[nb][2], sacc[nb][3]));
        }
        #pragma unroll
        for (int j = 0; j < 2; j++) {
            rm[j] = fmaxf(rm[j], __shfl_xor_sync(0xffffffffu, rm[j], 1));
            rm[j] = fmaxf(rm[j], __shfl_xor_sync(0xffffffffu, rm[j], 2));
        }
        float alpha[2];
        #pragma unroll
        for (int j = 0; j < 2; j++) {
            float mn = fmaxf(mi[j], rm[j]);
            alpha[j] = __expf(mi[j] - mn);
            mi[j] = mn;
        }
        float rs[2] = {0.f, 0.f};
        #pragma unroll
        for (int nb = 0; nb < 8; nb++) {
            float p0 = __expf(sacc[nb][0] - mi[0]);
            float p1 = __expf(sacc[nb][1] - mi[0]);
            float p2 = __expf(sacc[nb][2] - mi[1]);
            float p3 = __expf(sacc[nb][3] - mi[1]);
            sacc[nb][0] = p0; sacc[nb][1] = p1;
            sacc[nb][2] = p2; sacc[nb][3] = p3;
            rs[0] += p0 + p1;
            rs[1] += p2 + p3;
        }
        #pragma unroll
        for (int j = 0; j < 2; j++) {
            rs[j] += __shfl_xor_sync(0xffffffffu, rs[j], 1);
            rs[j] += __shfl_xor_sync(0xffffffffu, rs[j], 2);
            li[j] = li[j] * alpha[j] + rs[j];
        }
        #pragma unroll
        for (int nb = 0; nb < 8; nb++) {
            oacc[nb][0] *= alpha[0]; oacc[nb][1] *= alpha[0];
            oacc[nb][2] *= alpha[1]; oacc[nb][3] *= alpha[1];
        }

        uint32_t pf[2][4][4];
        #pragma unroll
        for (int ks = 0; ks < 4; ks++) {
            split_pack2(sacc[2 * ks][0],     sacc[2 * ks][1],     pf[0][ks][0], pf[1][ks][0]);
            split_pack2(sacc[2 * ks][2],     sacc[2 * ks][3],     pf[0][ks][1], pf[1][ks][1]);
            split_pack2(sacc[2 * ks + 1][0], sacc[2 * ks + 1][1], pf[0][ks][2], pf[1][ks][2]);
            split_pack2(sacc[2 * ks + 1][2], sacc[2 * ks + 1][3], pf[0][ks][3], pf[1][ks][3]);
        }

        #pragma unroll
        for (int ks = 0; ks < 4; ks++) {
            uint32_t vfh[8][2], vfl[8][2];
            #pragma unroll
            for (int nb = 0; nb < 4; nb++) {
                uint32_t addr = s0 + 2 * KVARR + (nb * 16 + b_r) * FSTR + (ks * 2 + b_c) * 16;
                uint32_t t0, t1, t2, t3;
                LDSM4(t0, t1, t2, t3, addr);
                vfh[2 * nb][0] = t0; vfh[2 * nb][1] = t1;
                vfh[2 * nb + 1][0] = t2; vfh[2 * nb + 1][1] = t3;
                LDSM4(t0, t1, t2, t3, addr + KVARR);
                vfl[2 * nb][0] = t0; vfl[2 * nb][1] = t1;
                vfl[2 * nb + 1][0] = t2; vfl[2 * nb + 1][1] = t3;
            }
            #pragma unroll
            for (int nb = 0; nb < 8; nb++) {
                MMA16816(oacc[nb], pf[0][ks], vfh[nb]);
                MMA16816(oacc[nb], pf[0][ks], vfl[nb]);
                MMA16816(oacc[nb], pf[1][ks], vfh[nb]);
            }
        }
    }

    const float inv0 = 1.f / li[0];
    const float inv1 = 1.f / li[1];
    const size_t m0 = mbase + qbase + r0loc;
    #pragma unroll
    for (int nb = 0; nb < 8; nb++) {
        const int col = h * HDIM + nb * 8 + (lane & 3) * 2;
        uint32_t hi, lo;
        split_pack2(oacc[nb][0] * inv0, oacc[nb][1] * inv0, hi, lo);
        *(uint32_t*)(g_aoh + m0 * DD + col) = hi;
        *(uint32_t*)(g_aol + m0 * DD + col) = lo;
        split_pack2(oacc[nb][2] * inv1, oacc[nb][3] * inv1, hi, lo);
        *(uint32_t*)(g_aoh + (m0 + 8) * DD + col) = hi;
        *(uint32_t*)(g_aol + (m0 + 8) * DD + col) = lo;
    }
}

// ---------------------------------------------------------------------------
// kernel_launch
// ---------------------------------------------------------------------------
extern "C" void kernel_launch(void* const* d_in, const int* in_sizes, int n_in,
                              void* d_out, int out_size) {
    const float* x  = (const float*)d_in[0];
    float* out = (float*)d_out;

    __nv_bfloat16 *xh, *xl, *aoh, *aol, *wth, *wtl;
    cudaGetSymbolAddress((void**)&xh,  g_xh);
    cudaGetSymbolAddress((void**)&xl,  g_xl);
    cudaGetSymbolAddress((void**)&aoh, g_aoh);
    cudaGetSymbolAddress((void**)&aol, g_aol);
    cudaGetSymbolAddress((void**)&wth, g_wth);
    cudaGetSymbolAddress((void**)&wtl, g_wtl);

    cudaFuncSetAttribute(gemm_qkv, cudaFuncAttributeMaxDynamicSharedMemorySize,
                         SMEM_GEMM);
    cudaFuncSetAttribute(gemm_one, cudaFuncAttributeMaxDynamicSharedMemorySize,
                         SMEM_GEMM);
    cudaFuncSetAttribute(flash_tc, cudaFuncAttributeMaxDynamicSharedMemorySize,
                         SMEM_FLASH);

    // Fused prep: weight transpose+split AND activation split, one launch
    prep_kernel<<<8192, 256>>>(x, (const float*)d_in[2], (const float*)d_in[3],
                               (const float*)d_in[4], (const float*)d_in[5]);

    // QKV projections (bf16x3 HMMA)
    gemm_qkv<<<dim3(24, 32), 256, SMEM_GEMM>>>(xh, xl, wth, wtl);

    // Fused mid: RoPE+split Q/K AND V transpose+split, one launch
    mid_kernel<<<12288, 256>>>();

    // Flash attention (writes split ao directly)
    flash_tc<<<dim3(NQT, BB * HH), 256, SMEM_FLASH>>>();

    // Output projection
    gemm_one<<<dim3(8, 32), 256, SMEM_GEMM>>>(aoh, aol, wth + 3 * (size_t)DD * DD,
                                              wtl + 3 * (size_t)DD * DD, out);
}

// round 15
// speedup vs baseline: 1.5303x; 1.5303x over previous
#include <cuda_runtime.h>
#include <cuda_bf16.h>
#include <math.h>
#include <stdint.h>

// Problem constants
#define BB 2
#define SS 2048
#define DD 1024
#define HH 16
#define HDIM 64
#define MM (BB*SS)          // 4096 total rows
#define NQT 16              // q tiles of 128 per (b,h)

// ---------------------------------------------------------------------------
// Scratch (device globals — no allocations allowed)
// ---------------------------------------------------------------------------
__device__ float g_q [MM*DD];
__device__ float g_k [MM*DD];
__device__ float g_v [MM*DD];
__device__ __nv_bfloat16 g_xh [MM*DD];
__device__ __nv_bfloat16 g_xl [MM*DD];
__device__ __nv_bfloat16 g_aoh[MM*DD];
__device__ __nv_bfloat16 g_aol[MM*DD];
__device__ __nv_bfloat16 g_wth[4][DD*DD];
__device__ __nv_bfloat16 g_wtl[4][DD*DD];
// flash operands (post-RoPE, bf16x3 split)
__device__ __nv_bfloat16 g_qh [MM*DD];
__device__ __nv_bfloat16 g_ql [MM*DD];
__device__ __nv_bfloat16 g_kh [MM*DD];
__device__ __nv_bfloat16 g_kl [MM*DD];
__device__ __nv_bfloat16 g_vth[BB*HH*HDIM*SS];  // [bh][d][s]
__device__ __nv_bfloat16 g_vtl[BB*HH*HDIM*SS];

// ---------------------------------------------------------------------------
// PTX helpers (sm_80-class only — valid for compute_103 w/o 'a' suffix)
// ---------------------------------------------------------------------------
__device__ __forceinline__ uint32_t smem_u32(const void* p) {
    uint32_t a;
    asm("{ .reg .u64 t; cvta.to.shared.u64 t, %1; cvt.u32.u64 %0, t; }"
        : "=r"(a) : "l"(p));
    return a;
}

#define LDSM4(R0, R1, R2, R3, addr) \
    asm volatile("ldmatrix.sync.aligned.m8n8.x4.shared.b16 {%0,%1,%2,%3}, [%4];" \
                 : "=r"(R0), "=r"(R1), "=r"(R2), "=r"(R3) : "r"(addr))

#define MMA16816(d, a, b) \
    asm volatile("mma.sync.aligned.m16n8k16.row.col.f32.bf16.bf16.f32 " \
                 "{%0,%1,%2,%3}, {%4,%5,%6,%7}, {%8,%9}, {%0,%1,%2,%3};" \
                 : "+f"((d)[0]), "+f"((d)[1]), "+f"((d)[2]), "+f"((d)[3]) \
                 : "r"((a)[0]), "r"((a)[1]), "r"((a)[2]), "r"((a)[3]), \
                   "r"((b)[0]), "r"((b)[1]))

#define CP_ASYNC16(s, g) \
    asm volatile("cp.async.cg.shared.global [%0], [%1], 16;" :: "r"(s), "l"(g))
#define CP_COMMIT() asm volatile("cp.async.commit_group;" ::: "memory")
#define CP_WAIT1()  asm volatile("cp.async.wait_group 1;" ::: "memory")
#define CP_WAIT0()  asm volatile("cp.async.wait_group 0;" ::: "memory")

__device__ __forceinline__ void split_pack2(float x, float y,
                                            uint32_t& hi, uint32_t& lo) {
    __nv_bfloat16 hx = __float2bfloat16(x), hy = __float2bfloat16(y);
    __nv_bfloat16 lx = __float2bfloat16(x - __bfloat162float(hx));
    __nv_bfloat16 ly = __float2bfloat16(y - __bfloat162float(hy));
    hi = (uint32_t)__bfloat16_as_ushort(hx) | ((uint32_t)__bfloat16_as_ushort(hy) << 16);
    lo = (uint32_t)__bfloat16_as_ushort(lx) | ((uint32_t)__bfloat16_as_ushort(ly) << 16);
}

// ---------------------------------------------------------------------------
// Split fp32 -> (hi bf16, lo bf16)
// ---------------------------------------------------------------------------
__global__ __launch_bounds__(256) void split_f32(const float* __restrict__ src,
                                                 __nv_bfloat16* __restrict__ hi,
                                                 __nv_bfloat16* __restrict__ lo,
                                                 int n4) {
    int i = blockIdx.x * blockDim.x + threadIdx.x;
    if (i >= n4) return;
    float4 v = ((const float4*)src)[i];
    float vv[4] = {v.x, v.y, v.z, v.w};
    __nv_bfloat16 h[4], l[4];
    #pragma unroll
    for (int j = 0; j < 4; j++) {
        h[j] = __float2bfloat16(vv[j]);
        l[j] = __float2bfloat16(vv[j] - __bfloat162float(h[j]));
    }
    ((__nv_bfloat162*)hi)[2 * i + 0] = __nv_bfloat162(h[0], h[1]);
    ((__nv_bfloat162*)hi)[2 * i + 1] = __nv_bfloat162(h[2], h[3]);
    ((__nv_bfloat162*)lo)[2 * i + 0] = __nv_bfloat162(l[0], l[1]);
    ((__nv_bfloat162*)lo)[2 * i + 1] = __nv_bfloat162(l[2], l[3]);
}

// ---------------------------------------------------------------------------
// Transpose + split ALL 4 weights in one launch: grid.z = weight index.
// ---------------------------------------------------------------------------
__global__ void transpose_split4(const float* __restrict__ W0,
                                 const float* __restrict__ W1,
                                 const float* __restrict__ W2,
                                 const float* __restrict__ W3) {
    __shared__ float t[32][33];
    const float* W = (blockIdx.z == 0) ? W0 : (blockIdx.z == 1) ? W1 :
                     (blockIdx.z == 2) ? W2 : W3;
    __nv_bfloat16* th = g_wth[blockIdx.z];
    __nv_bfloat16* tl = g_wtl[blockIdx.z];
    int tx = threadIdx.x, ty = threadIdx.y;          // 32 x 8
    int n0 = blockIdx.x * 32, k0 = blockIdx.y * 32;
    #pragma unroll
    for (int r = 0; r < 4; r++)
        t[ty + 8 * r][tx] = W[(size_t)(k0 + ty + 8 * r) * DD + n0 + tx];
    __syncthreads();
    #pragma unroll
    for (int r = 0; r < 4; r++) {
        float v = t[tx][ty + 8 * r];
        __nv_bfloat16 h = __float2bfloat16(v);
        __nv_bfloat16 l = __float2bfloat16(v - __bfloat162float(h));
        size_t idx = (size_t)(n0 + ty + 8 * r) * DD + k0 + tx;
        th[idx] = h;
        tl[idx] = l;
    }
}

// ---------------------------------------------------------------------------
// V transpose+split per (b,h): g_v[m][1024] -> g_vth/l [bh][d][s]
// ---------------------------------------------------------------------------
__global__ void vtrans_split() {
    __shared__ float t[32][33];
    int tx = threadIdx.x, ty = threadIdx.y;   // 32 x 8
    int s0 = blockIdx.x * 32, d0 = blockIdx.y * 32;
    int bh = blockIdx.z;
    int b = bh >> 4, h = bh & 15;
    #pragma unroll
    for (int r = 0; r < 4; r++)
        t[ty + 8 * r][tx] = g_v[(size_t)(b * SS + s0 + ty + 8 * r) * DD + h * HDIM + d0 + tx];
    __syncthreads();
    #pragma unroll
    for (int r = 0; r < 4; r++) {
        float v = t[tx][ty + 8 * r];
        __nv_bfloat16 hi = __float2bfloat16(v);
        __nv_bfloat16 lo = __float2bfloat16(v - __bfloat162float(hi));
        size_t idx = ((size_t)bh * HDIM + d0 + ty + 8 * r) * SS + s0 + tx;
        g_vth[idx] = hi;
        g_vtl[idx] = lo;
    }
}

// ---------------------------------------------------------------------------
// RoPE + split: reads g_q/g_k fp32, writes split bf16 qh/ql/kh/kl.
// ---------------------------------------------------------------------------
__global__ __launch_bounds__(256) void rope_split() {
    int idx = blockIdx.x * blockDim.x + threadIdx.x;
    int j = idx & 31;
    int h = (idx >> 5) & (HH - 1);
    int m = idx >> 9;
    int pos = m & (SS - 1);

    float freq = expf(-(float)j * (9.210340371976184f / 32.0f));
    float sn, cs;
    sincosf((float)pos * freq, &sn, &cs);

    int base = m * DD + h * HDIM;
    float q1 = g_q[base + j], q2 = g_q[base + j + 32];
    float k1 = g_k[base + j], k2 = g_k[base + j + 32];
    float qa = q1 * cs - q2 * sn;
    float qb = q2 * cs + q1 * sn;
    float ka = k1 * cs - k2 * sn;
    float kb = k2 * cs + k1 * sn;

    __nv_bfloat16 t;
    t = __float2bfloat16(qa); g_qh[base + j] = t;
    g_ql[base + j] = __float2bfloat16(qa - __bfloat162float(t));
    t = __float2bfloat16(qb); g_qh[base + j + 32] = t;
    g_ql[base + j + 32] = __float2bfloat16(qb - __bfloat162float(t));
    t = __float2bfloat16(ka); g_kh[base + j] = t;
    g_kl[base + j] = __float2bfloat16(ka - __bfloat162float(t));
    t = __float2bfloat16(kb); g_kh[base + j + 32] = t;
    g_kl[base + j + 32] = __float2bfloat16(kb - __bfloat162float(t));
}

// ---------------------------------------------------------------------------
// bf16x3 HMMA GEMM (proven R6/R9 core): C = (Ah+Al)*(Bh+Bl)^T, 3 MMA terms.
// 128x128 CTA tile, BK=32, 8 warps (64x32 warp tiles), 2-stage cp.async.
// ---------------------------------------------------------------------------
#define PA 80
#define ARR_BYTES (128 * PA)
#define STAGE_BYTES (4 * ARR_BYTES)
#define SMEM_GEMM (2 * STAGE_BYTES)

__device__ __forceinline__ void gemm_body(const __nv_bfloat16* __restrict__ Ah,
                                          const __nv_bfloat16* __restrict__ Al,
                                          const __nv_bfloat16* __restrict__ Bh,
                                          const __nv_bfloat16* __restrict__ Bl,
                                          float* __restrict__ C,
                                          int rowBase, int colBase,
                                          char* smem) {
    const int tid = threadIdx.x;
    const int lane = tid & 31;
    const int wid = tid >> 5;
    const int wm = wid >> 2;
    const int wn = wid & 3;
    const uint32_t sb = smem_u32(smem);

    const int lr = tid >> 2;
    const int lc = tid & 3;

    float acc[4][4][4];
    #pragma unroll
    for (int i = 0; i < 4; i++)
        #pragma unroll
        for (int j = 0; j < 4; j++)
            #pragma unroll
            for (int r = 0; r < 4; r++) acc[i][j][r] = 0.f;

    const int a_r = (lane & 15);
    const int a_c = (lane >> 4);
    const int b_r = (lane & 7) + ((lane >> 4) << 3);
    const int b_c = (lane >> 3) & 1;

    auto load_stage = [&](int kb, int stage) {
        const uint32_t s0 = sb + stage * STAGE_BYTES;
        const int kOff = kb * 32 + lc * 8;
        #pragma unroll
        for (int half = 0; half < 2; half++) {
            const int r = lr + half * 64;
            const uint32_t sa = s0 + r * PA + lc * 16;
            const size_t gA = (size_t)(rowBase + r) * DD + kOff;
            const size_t gB = (size_t)(colBase + r) * DD + kOff;
            CP_ASYNC16(sa + 0 * ARR_BYTES, Ah + gA);
            CP_ASYNC16(sa + 1 * ARR_BYTES, Al + gA);
            CP_ASYNC16(sa + 2 * ARR_BYTES, Bh + gB);
            CP_ASYNC16(sa + 3 * ARR_BYTES, Bl + gB);
        }
        CP_COMMIT();
    };

    load_stage(0, 0);

    for (int kb = 0; kb < 32; kb++) {
        if (kb + 1 < 32) {
            load_stage(kb + 1, (kb + 1) & 1);
            CP_WAIT1();
        } else {
            CP_WAIT0();
        }
        __syncthreads();

        const uint32_t s0 = sb + (kb & 1) * STAGE_BYTES;
        const uint32_t sAh = s0 + 0 * ARR_BYTES;
        const uint32_t sAl = s0 + 1 * ARR_BYTES;
        const uint32_t sBh = s0 + 2 * ARR_BYTES;
        const uint32_t sBl = s0 + 3 * ARR_BYTES;

        #pragma unroll
        for (int ks = 0; ks < 2; ks++) {
            uint32_t ah[4][4], al[4][4], bh[4][2], bl[4][2];
            const int kc0 = ks * 2;
            #pragma unroll
            for (int ma = 0; ma < 4; ma++) {
                const int row = wm * 64 + ma * 16 + a_r;
                const uint32_t addr = row * PA + (kc0 + a_c) * 16;
                LDSM4(ah[ma][0], ah[ma][1], ah[ma][2], ah[ma][3], sAh + addr);
                LDSM4(al[ma][0], al[ma][1], al[ma][2], al[ma][3], sAl + addr);
            }
            #pragma unroll
            for (int nb = 0; nb < 2; nb++) {
                const int row = wn * 32 + nb * 16 + b_r;
                const uint32_t addr = row * PA + (kc0 + b_c) * 16;
                uint32_t t0, t1, t2, t3;
                LDSM4(t0, t1, t2, t3, sBh + addr);
                bh[2 * nb][0] = t0; bh[2 * nb][1] = t1;
                bh[2 * nb + 1][0] = t2; bh[2 * nb + 1][1] = t3;
                LDSM4(t0, t1, t2, t3, sBl + addr);
                bl[2 * nb][0] = t0; bl[2 * nb][1] = t1;
                bl[2 * nb + 1][0] = t2; bl[2 * nb + 1][1] = t3;
            }
            #pragma unroll
            for (int ma = 0; ma < 4; ma++)
                #pragma unroll
                for (int na = 0; na < 4; na++) {
                    MMA16816(acc[ma][na], ah[ma], bh[na]);
                    MMA16816(acc[ma][na], ah[ma], bl[na]);
                    MMA16816(acc[ma][na], al[ma], bh[na]);
                }
        }
        __syncthreads();
    }

    const int er = lane >> 2;
    const int ec = (lane & 3) * 2;
    #pragma unroll
    for (int ma = 0; ma < 4; ma++) {
        const int row0 = rowBase + wm * 64 + ma * 16 + er;
        #pragma unroll
        for (int na = 0; na < 4; na++) {
            const int col = colBase + wn * 32 + na * 8 + ec;
            *(float2*)&C[(size_t)row0 * DD + col] =
                make_float2(acc[ma][na][0], acc[ma][na][1]);
            *(float2*)&C[(size_t)(row0 + 8) * DD + col] =
                make_float2(acc[ma][na][2], acc[ma][na][3]);
        }
    }
}

__global__ __launch_bounds__(256) void gemm_qkv(const __nv_bfloat16* __restrict__ xh,
                                                const __nv_bfloat16* __restrict__ xl,
                                                const __nv_bfloat16* __restrict__ wth,
                                                const __nv_bfloat16* __restrict__ wtl) {
    extern __shared__ char smem[];
    const int gw = blockIdx.x >> 3;
    const int colBase = (blockIdx.x & 7) * 128;
    const int rowBase = blockIdx.y * 128;
    float* C = (gw == 0) ? g_q : (gw == 1) ? g_k : g_v;
    const __nv_bfloat16* Bh = wth + (size_t)gw * DD * DD;
    const __nv_bfloat16* Bl = wtl + (size_t)gw * DD * DD;
    gemm_body(xh, xl, Bh, Bl, C, rowBase, colBase, smem);
}

__global__ __launch_bounds__(256) void gemm_one(const __nv_bfloat16* __restrict__ Ah,
                                                const __nv_bfloat16* __restrict__ Al,
                                                const __nv_bfloat16* __restrict__ Bh,
                                                const __nv_bfloat16* __restrict__ Bl,
                                                float* __restrict__ C) {
    extern __shared__ char smem[];
    gemm_body(Ah, Al, Bh, Bl, C, blockIdx.y * 128, blockIdx.x * 128, smem);
}

// ---------------------------------------------------------------------------
// Tensor-core causal flash attention (bf16x3, proven R6/R9/R11 core).
// Epilogue writes split bf16 aoh/aol directly.
// ---------------------------------------------------------------------------
#define FSTR 144
#define QAREA (128 * FSTR)
#define KVARR (64 * FSTR)
#define KVSTAGE (4 * KVARR)
#define SMEM_FLASH (2 * KVSTAGE)

__global__ __launch_bounds__(256, 1) void flash_tc() {
    extern __shared__ char smc[];
    const uint32_t sb = smem_u32(smc);
    const int tid = threadIdx.x, lane = tid & 31, warp = tid >> 5;
    const int qt = (NQT - 1) - blockIdx.x;
    const int bh = blockIdx.y;
    const int b = bh >> 4, h = bh & 15;
    const int qbase = qt * 128;
    const size_t mbase = (size_t)b * SS;

    {
        const int r = tid >> 1;
        const int c0 = (tid & 1) * 4;
        const size_t g = (mbase + qbase + r) * DD + (size_t)h * HDIM;
        #pragma unroll
        for (int it = 0; it < 4; it++) {
            int c = c0 + it;
            CP_ASYNC16(sb + r * FSTR + c * 16, g_qh + g + c * 8);
            CP_ASYNC16(sb + QAREA + r * FSTR + c * 16, g_ql + g + c * 8);
        }
        CP_COMMIT();
    }
    CP_WAIT0();
    __syncthreads();

    uint32_t qf[2][4][4];
    {
        const int a_r = lane & 15, a_c = lane >> 4;
        #pragma unroll
        for (int ks = 0; ks < 4; ks++) {
            uint32_t addr = sb + (warp * 16 + a_r) * FSTR + (ks * 2 + a_c) * 16;
            LDSM4(qf[0][ks][0], qf[0][ks][1], qf[0][ks][2], qf[0][ks][3], addr);
            LDSM4(qf[1][ks][0], qf[1][ks][1], qf[1][ks][2], qf[1][ks][3], addr + QAREA);
        }
    }
    __syncthreads();

    float mi[2] = {-3.0e38f, -3.0e38f};
    float li[2] = {0.f, 0.f};
    float oacc[8][4];
    #pragma unroll
    for (int i = 0; i < 8; i++)
        #pragma unroll
        for (int j = 0; j < 4; j++) oacc[i][j] = 0.f;

    auto load_kv = [&](int kt, int stage) {
        const uint32_t s0 = sb + stage * KVSTAGE;
        const int r = tid >> 2;
        const int cb = tid & 3;
        const size_t gk = (mbase + kt * 64 + r) * DD + (size_t)h * HDIM;
        const size_t gv = ((size_t)bh * HDIM + r) * SS + kt * 64;
        #pragma unroll
        for (int cc = 0; cc < 2; cc++) {
            const int c = cb + cc * 4;
            const uint32_t sa = s0 + r * FSTR + c * 16;
            CP_ASYNC16(sa + 0 * KVARR, g_kh + gk + c * 8);
            CP_ASYNC16(sa + 1 * KVARR, g_kl + gk + c * 8);
            CP_ASYNC16(sa + 2 * KVARR, g_vth + gv + c * 8);
            CP_ASYNC16(sa + 3 * KVARR, g_vtl + gv + c * 8);
        }
        CP_COMMIT();
    };

    const int nt = 2 * qt + 2;
    load_kv(0, 0);

    const int b_r = (lane & 7) + ((lane >> 4) << 3);
    const int b_c = (lane >> 3) & 1;
    const int r0loc = warp * 16 + (lane >> 2);
    const float scale = 0.125f;

    for (int kt = 0; kt < nt; kt++) {
        CP_WAIT0();
        __syncthreads();
        if (kt + 1 < nt) load_kv(kt + 1, (kt + 1) & 1);

        const uint32_t s0 = sb + (kt & 1) * KVSTAGE;

        float sacc[8][4];
        #pragma unroll
        for (int i = 0; i < 8; i++)
            #pragma unroll
            for (int j = 0; j < 4; j++) sacc[i][j] = 0.f;

        #pragma unroll
        for (int ks = 0; ks < 4; ks++) {
            uint32_t kfh[8][2], kfl[8][2];
            #pragma unroll
            for (int nb = 0; nb < 4; nb++) {
                uint32_t addr = s0 + (nb * 16 + b_r) * FSTR + (ks * 2 + b_c) * 16;
                uint32_t t0, t1, t2, t3;
                LDSM4(t0, t1, t2, t3, addr);
                kfh[2 * nb][0] = t0; kfh[2 * nb][1] = t1;
                kfh[2 * nb + 1][0] = t2; kfh[2 * nb + 1][1] = t3;
                LDSM4(t0, t1, t2, t3, addr + KVARR);
                kfl[2 * nb][0] = t0; kfl[2 * nb][1] = t1;
                kfl[2 * nb + 1][0] = t2; kfl[2 * nb + 1][1] = t3;
            }
            #pragma unroll
            for (int nb = 0; nb < 8; nb++) {
                MMA16816(sacc[nb], qf[0][ks], kfh[nb]);
                MMA16816(sacc[nb], qf[0][ks], kfl[nb]);
                MMA16816(sacc[nb], qf[1][ks], kfh[nb]);
            }
        }

        const bool diag = (kt >= 2 * qt);
        #pragma unroll
        for (int nb = 0; nb < 8; nb++)
            #pragma unroll
            for (int e = 0; e < 4; e++) {
                float s = sacc[nb][e] * scale;
                if (diag) {
                    int row = qbase + r0loc + ((e >= 2) ? 8 : 0);
                    int col = kt * 64 + nb * 8 + (lane & 3) * 2 + (e & 1);
                    if (col > row) s = -3.0e38f;
                }
                sacc[nb][e] = s;
            }

        float rm[2] = {-3.0e38f, -3.0e38f};
        #pragma unroll
        for (int nb = 0; nb < 8; nb++) {
            rm[0] = fmaxf(rm[0], fmaxf(sacc[nb][0], sacc[nb][1]));
            rm[1] = fmaxf(rm[1], fmaxf(sacc[nb][2], sacc[nb][3]));
        }
        #pragma unroll
        for (int j = 0; j < 2; j++) {
            rm[j] = fmaxf(rm[j], __shfl_xor_sync(0xffffffffu, rm[j], 1));
            rm[j] = fmaxf(rm[j], __shfl_xor_sync(0xffffffffu, rm[j], 2));
        }
        float alpha[2];
        #pragma unroll
        for (int j = 0; j < 2; j++) {
            float mn = fmaxf(mi[j], rm[j]);
            alpha[j] = __expf(mi[j] - mn);
            mi[j] = mn;
        }
        float rs[2] = {0.f, 0.f};
        #pragma unroll
        for (int nb = 0; nb < 8; nb++) {
            float p0 = __expf(sacc[nb][0] - mi[0]);
            float p1 = __expf(sacc[nb][1] - mi[0]);
            float p2 = __expf(sacc[nb][2] - mi[1]);
            float p3 = __expf(sacc[nb][3] - mi[1]);
            sacc[nb][0] = p0; sacc[nb][1] = p1;
            sacc[nb][2] = p2; sacc[nb][3] = p3;
            rs[0] += p0 + p1;
            rs[1] += p2 + p3;
        }
        #pragma unroll
        for (int j = 0; j < 2; j++) {
            rs[j] += __shfl_xor_sync(0xffffffffu, rs[j], 1);
            rs[j] += __shfl_xor_sync(0xffffffffu, rs[j], 2);
            li[j] = li[j] * alpha[j] + rs[j];
        }
        #pragma unroll
        for (int nb = 0; nb < 8; nb++) {
            oacc[nb][0] *= alpha[0]; oacc[nb][1] *= alpha[0];
            oacc[nb][2] *= alpha[1]; oacc[nb][3] *= alpha[1];
        }

        uint32_t pf[2][4][4];
        #pragma unroll
        for (int ks = 0; ks < 4; ks++) {
            split_pack2(sacc[2 * ks][0],     sacc[2 * ks][1],     pf[0][ks][0], pf[1][ks][0]);
            split_pack2(sacc[2 * ks][2],     sacc[2 * ks][3],     pf[0][ks][1], pf[1][ks][1]);
            split_pack2(sacc[2 * ks + 1][0], sacc[2 * ks + 1][1], pf[0][ks][2], pf[1][ks][2]);
            split_pack2(sacc[2 * ks + 1][2], sacc[2 * ks + 1][3], pf[0][ks][3], pf[1][ks][3]);
        }

        #pragma unroll
        for (int ks = 0; ks < 4; ks++) {
            uint32_t vfh[8][2], vfl[8][2];
            #pragma unroll
            for (int nb = 0; nb < 4; nb++) {
                uint32_t addr = s0 + 2 * KVARR + (nb * 16 + b_r) * FSTR + (ks * 2 + b_c) * 16;
                uint32_t t0, t1, t2, t3;
                LDSM4(t0, t1, t2, t3, addr);
                vfh[2 * nb][0] = t0; vfh[2 * nb][1] = t1;
                vfh[2 * nb + 1][0] = t2; vfh[2 * nb + 1][1] = t3;
                LDSM4(t0, t1, t2, t3, addr + KVARR);
                vfl[2 * nb][0] = t0; vfl[2 * nb][1] = t1;
                vfl[2 * nb + 1][0] = t2; vfl[2 * nb + 1][1] = t3;
            }
            #pragma unroll
            for (int nb = 0; nb < 8; nb++) {
                MMA16816(oacc[nb], pf[0][ks], vfh[nb]);
                MMA16816(oacc[nb], pf[0][ks], vfl[nb]);
                MMA16816(oacc[nb], pf[1][ks], vfh[nb]);
            }
        }
    }

    // epilogue: write split bf16 ao directly
    const float inv0 = 1.f / li[0];
    const float inv1 = 1.f / li[1];
    const size_t m0 = mbase + qbase + r0loc;
    #pragma unroll
    for (int nb = 0; nb < 8; nb++) {
        const int col = h * HDIM + nb * 8 + (lane & 3) * 2;
        uint32_t hi, lo;
        split_pack2(oacc[nb][0] * inv0, oacc[nb][1] * inv0, hi, lo);
        *(uint32_t*)(g_aoh + m0 * DD + col) = hi;
        *(uint32_t*)(g_aol + m0 * DD + col) = lo;
        split_pack2(oacc[nb][2] * inv1, oacc[nb][3] * inv1, hi, lo);
        *(uint32_t*)(g_aoh + (m0 + 8) * DD + col) = hi;
        *(uint32_t*)(g_aol + (m0 + 8) * DD + col) = lo;
    }
}

// ---------------------------------------------------------------------------
// kernel_launch
// ---------------------------------------------------------------------------
extern "C" void kernel_launch(void* const* d_in, const int* in_sizes, int n_in,
                              void* d_out, int out_size) {
    const float* x  = (const float*)d_in[0];
    float* out = (float*)d_out;

    __nv_bfloat16 *xh, *xl, *aoh, *aol, *wth, *wtl;
    cudaGetSymbolAddress((void**)&xh,  g_xh);
    cudaGetSymbolAddress((void**)&xl,  g_xl);
    cudaGetSymbolAddress((void**)&aoh, g_aoh);
    cudaGetSymbolAddress((void**)&aol, g_aol);
    cudaGetSymbolAddress((void**)&wth, g_wth);
    cudaGetSymbolAddress((void**)&wtl, g_wtl);

    cudaFuncSetAttribute(gemm_qkv, cudaFuncAttributeMaxDynamicSharedMemorySize,
                         SMEM_GEMM);
    cudaFuncSetAttribute(gemm_one, cudaFuncAttributeMaxDynamicSharedMemorySize,
                         SMEM_GEMM);
    cudaFuncSetAttribute(flash_tc, cudaFuncAttributeMaxDynamicSharedMemorySize,
                         SMEM_FLASH);

    dim3 tt(32, 8);
    transpose_split4<<<dim3(32, 32, 4), tt>>>((const float*)d_in[2],
                                              (const float*)d_in[3],
                                              (const float*)d_in[4],
                                              (const float*)d_in[5]);
    split_f32<<<4096, 256>>>(x, xh, xl, MM * DD / 4);

    // QKV projections (bf16x3 HMMA)
    gemm_qkv<<<dim3(24, 32), 256, SMEM_GEMM>>>(xh, xl, wth, wtl);

    // RoPE + split Q/K; transpose+split V
    rope_split<<<(MM * HH * 32) / 256, 256>>>();
    vtrans_split<<<dim3(64, 2, 32), tt>>>();

    // Flash attention (writes split ao directly)
    flash_tc<<<dim3(NQT, BB * HH), 256, SMEM_FLASH>>>();

    // Output projection
    gemm_one<<<dim3(8, 32), 256, SMEM_GEMM>>>(aoh, aol, wth + 3 * (size_t)DD * DD,
                                              wtl + 3 * (size_t)DD * DD, out);
}

// round 17
// speedup vs baseline: 1.5458x; 1.0102x over previous
#include <cuda_runtime.h>
#include <cuda_bf16.h>
#include <math.h>
#include <stdint.h>

// Problem constants
#define BB 2
#define SS 2048
#define DD 1024
#define HH 16
#define HDIM 64
#define MM (BB*SS)          // 4096 total rows
#define NQT 16              // q tiles of 128 per (b,h)

// ---------------------------------------------------------------------------
// Scratch (device globals — no allocations allowed)
// ---------------------------------------------------------------------------
__device__ float g_q [MM*DD];
__device__ float g_k [MM*DD];
__device__ float g_v [MM*DD];
__device__ __nv_bfloat16 g_xh [MM*DD];
__device__ __nv_bfloat16 g_xl [MM*DD];
__device__ __nv_bfloat16 g_aoh[MM*DD];
__device__ __nv_bfloat16 g_aol[MM*DD];
__device__ __nv_bfloat16 g_wth[4][DD*DD];
__device__ __nv_bfloat16 g_wtl[4][DD*DD];
// flash operands (post-RoPE, bf16x3 split)
__device__ __nv_bfloat16 g_qh [MM*DD];
__device__ __nv_bfloat16 g_ql [MM*DD];
__device__ __nv_bfloat16 g_kh [MM*DD];
__device__ __nv_bfloat16 g_kl [MM*DD];
__device__ __nv_bfloat16 g_vth[BB*HH*HDIM*SS];  // [bh][d][s]
__device__ __nv_bfloat16 g_vtl[BB*HH*HDIM*SS];

// ---------------------------------------------------------------------------
// PTX helpers (sm_80-class only — valid for compute_103 w/o 'a' suffix)
// ---------------------------------------------------------------------------
__device__ __forceinline__ uint32_t smem_u32(const void* p) {
    uint32_t a;
    asm("{ .reg .u64 t; cvta.to.shared.u64 t, %1; cvt.u32.u64 %0, t; }"
        : "=r"(a) : "l"(p));
    return a;
}

#define LDSM4(R0, R1, R2, R3, addr) \
    asm volatile("ldmatrix.sync.aligned.m8n8.x4.shared.b16 {%0,%1,%2,%3}, [%4];" \
                 : "=r"(R0), "=r"(R1), "=r"(R2), "=r"(R3) : "r"(addr))

#define MMA16816(d, a, b) \
    asm volatile("mma.sync.aligned.m16n8k16.row.col.f32.bf16.bf16.f32 " \
                 "{%0,%1,%2,%3}, {%4,%5,%6,%7}, {%8,%9}, {%0,%1,%2,%3};" \
                 : "+f"((d)[0]), "+f"((d)[1]), "+f"((d)[2]), "+f"((d)[3]) \
                 : "r"((a)[0]), "r"((a)[1]), "r"((a)[2]), "r"((a)[3]), \
                   "r"((b)[0]), "r"((b)[1]))

#define CP_ASYNC16(s, g) \
    asm volatile("cp.async.cg.shared.global [%0], [%1], 16;" :: "r"(s), "l"(g))
#define CP_COMMIT() asm volatile("cp.async.commit_group;" ::: "memory")
#define CP_WAIT1()  asm volatile("cp.async.wait_group 1;" ::: "memory")
#define CP_WAIT0()  asm volatile("cp.async.wait_group 0;" ::: "memory")

__device__ __forceinline__ void split_pack2(float x, float y,
                                            uint32_t& hi, uint32_t& lo) {
    __nv_bfloat16 hx = __float2bfloat16(x), hy = __float2bfloat16(y);
    __nv_bfloat16 lx = __float2bfloat16(x - __bfloat162float(hx));
    __nv_bfloat16 ly = __float2bfloat16(y - __bfloat162float(hy));
    hi = (uint32_t)__bfloat16_as_ushort(hx) | ((uint32_t)__bfloat16_as_ushort(hy) << 16);
    lo = (uint32_t)__bfloat16_as_ushort(lx) | ((uint32_t)__bfloat16_as_ushort(ly) << 16);
}

// ---------------------------------------------------------------------------
// prep_kernel: fused {transpose_split4 (blocks 0..4095)} ∪ {split_f32 x
// (blocks 4096..8191)}. Independent workloads, one launch.
// ---------------------------------------------------------------------------
__global__ __launch_bounds__(256) void prep_kernel(const float* __restrict__ x,
                                                   const float* __restrict__ W0,
                                                   const float* __restrict__ W1,
                                                   const float* __restrict__ W2,
                                                   const float* __restrict__ W3) {
    __shared__ float t[32][33];
    const int bx = blockIdx.x;
    const int tid = threadIdx.x;
    if (bx < 4096) {
        // transpose+split weights: decompose bx -> (n0:32, k0:32, w:4)
        const int w  = bx >> 10;
        const int rem = bx & 1023;
        const int n0 = (rem & 31) * 32;
        const int k0 = (rem >> 5) * 32;
        const float* W = (w == 0) ? W0 : (w == 1) ? W1 : (w == 2) ? W2 : W3;
        __nv_bfloat16* th = g_wth[w];
        __nv_bfloat16* tl = g_wtl[w];
        const int tx = tid & 31, ty = tid >> 5;   // 32 x 8
        #pragma unroll
        for (int r = 0; r < 4; r++)
            t[ty + 8 * r][tx] = W[(size_t)(k0 + ty + 8 * r) * DD + n0 + tx];
        __syncthreads();
        #pragma unroll
        for (int r = 0; r < 4; r++) {
            float v = t[tx][ty + 8 * r];
            __nv_bfloat16 h = __float2bfloat16(v);
            __nv_bfloat16 l = __float2bfloat16(v - __bfloat162float(h));
            size_t idx = (size_t)(n0 + ty + 8 * r) * DD + k0 + tx;
            th[idx] = h;
            tl[idx] = l;
        }
    } else {
        // split x -> xh/xl (1 float4 per thread)
        const int i = (bx - 4096) * 256 + tid;    // < MM*DD/4
        float4 v = ((const float4*)x)[i];
        float vv[4] = {v.x, v.y, v.z, v.w};
        __nv_bfloat16 h[4], l[4];
        #pragma unroll
        for (int j = 0; j < 4; j++) {
            h[j] = __float2bfloat16(vv[j]);
            l[j] = __float2bfloat16(vv[j] - __bfloat162float(h[j]));
        }
        ((__nv_bfloat162*)g_xh)[2 * i + 0] = __nv_bfloat162(h[0], h[1]);
        ((__nv_bfloat162*)g_xh)[2 * i + 1] = __nv_bfloat162(h[2], h[3]);
        ((__nv_bfloat162*)g_xl)[2 * i + 0] = __nv_bfloat162(l[0], l[1]);
        ((__nv_bfloat162*)g_xl)[2 * i + 1] = __nv_bfloat162(l[2], l[3]);
    }
}

// ---------------------------------------------------------------------------
// mid_kernel: fused {rope_split (blocks 0..8191)} ∪ {vtrans_split
// (blocks 8192..12287)}. Both depend only on gemm_qkv outputs.
// ---------------------------------------------------------------------------
__global__ __launch_bounds__(256) void mid_kernel() {
    __shared__ float t[32][33];
    const int bx = blockIdx.x;
    const int tid = threadIdx.x;
    if (bx < 8192) {
        // RoPE + split Q/K
        int idx = bx * 256 + tid;
        int j = idx & 31;
        int h = (idx >> 5) & (HH - 1);
        int m = idx >> 9;
        int pos = m & (SS - 1);

        float freq = expf(-(float)j * (9.210340371976184f / 32.0f));
        float sn, cs;
        sincosf((float)pos * freq, &sn, &cs);

        int base = m * DD + h * HDIM;
        float q1 = g_q[base + j], q2 = g_q[base + j + 32];
        float k1 = g_k[base + j], k2 = g_k[base + j + 32];
        float qa = q1 * cs - q2 * sn;
        float qb = q2 * cs + q1 * sn;
        float ka = k1 * cs - k2 * sn;
        float kb = k2 * cs + k1 * sn;

        __nv_bfloat16 tt;
        tt = __float2bfloat16(qa); g_qh[base + j] = tt;
        g_ql[base + j] = __float2bfloat16(qa - __bfloat162float(tt));
        tt = __float2bfloat16(qb); g_qh[base + j + 32] = tt;
        g_ql[base + j + 32] = __float2bfloat16(qb - __bfloat162float(tt));
        tt = __float2bfloat16(ka); g_kh[base + j] = tt;
        g_kl[base + j] = __float2bfloat16(ka - __bfloat162float(tt));
        tt = __float2bfloat16(kb); g_kh[base + j + 32] = tt;
        g_kl[base + j + 32] = __float2bfloat16(kb - __bfloat162float(tt));
    } else {
        // V transpose+split: decompose (bx-8192) -> (x:64, y:2, z:32)
        const int b2 = bx - 8192;
        const int s0 = (b2 & 63) * 32;
        const int d0 = ((b2 >> 6) & 1) * 32;
        const int bh = b2 >> 7;
        const int b = bh >> 4, h = bh & 15;
        const int tx = tid & 31, ty = tid >> 5;   // 32 x 8
        #pragma unroll
        for (int r = 0; r < 4; r++)
            t[ty + 8 * r][tx] = g_v[(size_t)(b * SS + s0 + ty + 8 * r) * DD + h * HDIM + d0 + tx];
        __syncthreads();
        #pragma unroll
        for (int r = 0; r < 4; r++) {
            float v = t[tx][ty + 8 * r];
            __nv_bfloat16 hi = __float2bfloat16(v);
            __nv_bfloat16 lo = __float2bfloat16(v - __bfloat162float(hi));
            size_t idx = ((size_t)bh * HDIM + d0 + ty + 8 * r) * SS + s0 + tx;
            g_vth[idx] = hi;
            g_vtl[idx] = lo;
        }
    }
}

// ---------------------------------------------------------------------------
// bf16x3 HMMA GEMM (proven R6/R9 core): C = (Ah+Al)*(Bh+Bl)^T, 3 MMA terms.
// ---------------------------------------------------------------------------
#define PA 80
#define ARR_BYTES (128 * PA)
#define STAGE_BYTES (4 * ARR_BYTES)
#define SMEM_GEMM (2 * STAGE_BYTES)

__device__ __forceinline__ void gemm_body(const __nv_bfloat16* __restrict__ Ah,
                                          const __nv_bfloat16* __restrict__ Al,
                                          const __nv_bfloat16* __restrict__ Bh,
                                          const __nv_bfloat16* __restrict__ Bl,
                                          float* __restrict__ C,
                                          int rowBase, int colBase,
                                          char* smem) {
    const int tid = threadIdx.x;
    const int lane = tid & 31;
    const int wid = tid >> 5;
    const int wm = wid >> 2;
    const int wn = wid & 3;
    const uint32_t sb = smem_u32(smem);

    const int lr = tid >> 2;
    const int lc = tid & 3;

    float acc[4][4][4];
    #pragma unroll
    for (int i = 0; i < 4; i++)
        #pragma unroll
        for (int j = 0; j < 4; j++)
            #pragma unroll
            for (int r = 0; r < 4; r++) acc[i][j][r] = 0.f;

    const int a_r = (lane & 15);
    const int a_c = (lane >> 4);
    const int b_r = (lane & 7) + ((lane >> 4) << 3);
    const int b_c = (lane >> 3) & 1;

    auto load_stage = [&](int kb, int stage) {
        const uint32_t s0 = sb + stage * STAGE_BYTES;
        const int kOff = kb * 32 + lc * 8;
        #pragma unroll
        for (int half = 0; half < 2; half++) {
            const int r = lr + half * 64;
            const uint32_t sa = s0 + r * PA + lc * 16;
            const size_t gA = (size_t)(rowBase + r) * DD + kOff;
            const size_t gB = (size_t)(colBase + r) * DD + kOff;
            CP_ASYNC16(sa + 0 * ARR_BYTES, Ah + gA);
            CP_ASYNC16(sa + 1 * ARR_BYTES, Al + gA);
            CP_ASYNC16(sa + 2 * ARR_BYTES, Bh + gB);
            CP_ASYNC16(sa + 3 * ARR_BYTES, Bl + gB);
        }
        CP_COMMIT();
    };

    load_stage(0, 0);

    for (int kb = 0; kb < 32; kb++) {
        if (kb + 1 < 32) {
            load_stage(kb + 1, (kb + 1) & 1);
            CP_WAIT1();
        } else {
            CP_WAIT0();
        }
        __syncthreads();

        const uint32_t s0 = sb + (kb & 1) * STAGE_BYTES;
        const uint32_t sAh = s0 + 0 * ARR_BYTES;
        const uint32_t sAl = s0 + 1 * ARR_BYTES;
        const uint32_t sBh = s0 + 2 * ARR_BYTES;
        const uint32_t sBl = s0 + 3 * ARR_BYTES;

        #pragma unroll
        for (int ks = 0; ks < 2; ks++) {
            uint32_t ah[4][4], al[4][4], bh[4][2], bl[4][2];
            const int kc0 = ks * 2;
            #pragma unroll
            for (int ma = 0; ma < 4; ma++) {
                const int row = wm * 64 + ma * 16 + a_r;
                const uint32_t addr = row * PA + (kc0 + a_c) * 16;
                LDSM4(ah[ma][0], ah[ma][1], ah[ma][2], ah[ma][3], sAh + addr);
                LDSM4(al[ma][0], al[ma][1], al[ma][2], al[ma][3], sAl + addr);
            }
            #pragma unroll
            for (int nb = 0; nb < 2; nb++) {
                const int row = wn * 32 + nb * 16 + b_r;
                const uint32_t addr = row * PA + (kc0 + b_c) * 16;
                uint32_t t0, t1, t2, t3;
                LDSM4(t0, t1, t2, t3, sBh + addr);
                bh[2 * nb][0] = t0; bh[2 * nb][1] = t1;
                bh[2 * nb + 1][0] = t2; bh[2 * nb + 1][1] = t3;
                LDSM4(t0, t1, t2, t3, sBl + addr);
                bl[2 * nb][0] = t0; bl[2 * nb][1] = t1;
                bl[2 * nb + 1][0] = t2; bl[2 * nb + 1][1] = t3;
            }
            #pragma unroll
            for (int ma = 0; ma < 4; ma++)
                #pragma unroll
                for (int na = 0; na < 4; na++) {
                    MMA16816(acc[ma][na], ah[ma], bh[na]);
                    MMA16816(acc[ma][na], ah[ma], bl[na]);
                    MMA16816(acc[ma][na], al[ma], bh[na]);
                }
        }
        __syncthreads();
    }

    const int er = lane >> 2;
    const int ec = (lane & 3) * 2;
    #pragma unroll
    for (int ma = 0; ma < 4; ma++) {
        const int row0 = rowBase + wm * 64 + ma * 16 + er;
        #pragma unroll
        for (int na = 0; na < 4; na++) {
            const int col = colBase + wn * 32 + na * 8 + ec;
            *(float2*)&C[(size_t)row0 * DD + col] =
                make_float2(acc[ma][na][0], acc[ma][na][1]);
            *(float2*)&C[(size_t)(row0 + 8) * DD + col] =
                make_float2(acc[ma][na][2], acc[ma][na][3]);
        }
    }
}

__global__ __launch_bounds__(256) void gemm_qkv(const __nv_bfloat16* __restrict__ xh,
                                                const __nv_bfloat16* __restrict__ xl,
                                                const __nv_bfloat16* __restrict__ wth,
                                                const __nv_bfloat16* __restrict__ wtl) {
    extern __shared__ char smem[];
    const int gw = blockIdx.x >> 3;
    const int colBase = (blockIdx.x & 7) * 128;
    const int rowBase = blockIdx.y * 128;
    float* C = (gw == 0) ? g_q : (gw == 1) ? g_k : g_v;
    const __nv_bfloat16* Bh = wth + (size_t)gw * DD * DD;
    const __nv_bfloat16* Bl = wtl + (size_t)gw * DD * DD;
    gemm_body(xh, xl, Bh, Bl, C, rowBase, colBase, smem);
}

__global__ __launch_bounds__(256) void gemm_one(const __nv_bfloat16* __restrict__ Ah,
                                                const __nv_bfloat16* __restrict__ Al,
                                                const __nv_bfloat16* __restrict__ Bh,
                                                const __nv_bfloat16* __restrict__ Bl,
                                                float* __restrict__ C) {
    extern __shared__ char smem[];
    gemm_body(Ah, Al, Bh, Bl, C, blockIdx.y * 128, blockIdx.x * 128, smem);
}

// ---------------------------------------------------------------------------
// Tensor-core causal flash attention (bf16x3, proven core).
// Epilogue writes split bf16 aoh/aol directly.
// ---------------------------------------------------------------------------
#define FSTR 144
#define QAREA (128 * FSTR)
#define KVARR (64 * FSTR)
#define KVSTAGE (4 * KVARR)
#define SMEM_FLASH (2 * KVSTAGE)

__global__ __launch_bounds__(256, 1) void flash_tc() {
    extern __shared__ char smc[];
    const uint32_t sb = smem_u32(smc);
    const int tid = threadIdx.x, lane = tid & 31, warp = tid >> 5;
    const int qt = (NQT - 1) - blockIdx.x;
    const int bh = blockIdx.y;
    const int b = bh >> 4, h = bh & 15;
    const int qbase = qt * 128;
    const size_t mbase = (size_t)b * SS;

    {
        const int r = tid >> 1;
        const int c0 = (tid & 1) * 4;
        const size_t g = (mbase + qbase + r) * DD + (size_t)h * HDIM;
        #pragma unroll
        for (int it = 0; it < 4; it++) {
            int c = c0 + it;
            CP_ASYNC16(sb + r * FSTR + c * 16, g_qh + g + c * 8);
            CP_ASYNC16(sb + QAREA + r * FSTR + c * 16, g_ql + g + c * 8);
        }
        CP_COMMIT();
    }
    CP_WAIT0();
    __syncthreads();

    uint32_t qf[2][4][4];
    {
        const int a_r = lane & 15, a_c = lane >> 4;
        #pragma unroll
        for (int ks = 0; ks < 4; ks++) {
            uint32_t addr = sb + (warp * 16 + a_r) * FSTR + (ks * 2 + a_c) * 16;
            LDSM4(qf[0][ks][0], qf[0][ks][1], qf[0][ks][2], qf[0][ks][3], addr);
            LDSM4(qf[1][ks][0], qf[1][ks][1], qf[1][ks][2], qf[1][ks][3], addr + QAREA);
        }
    }
    __syncthreads();

    float mi[2] = {-3.0e38f, -3.0e38f};
    float li[2] = {0.f, 0.f};
    float oacc[8][4];
    #pragma unroll
    for (int i = 0; i < 8; i++)
        #pragma unroll
        for (int j = 0; j < 4; j++) oacc[i][j] = 0.f;

    auto load_kv = [&](int kt, int stage) {
        const uint32_t s0 = sb + stage * KVSTAGE;
        const int r = tid >> 2;
        const int cb = tid & 3;
        const size_t gk = (mbase + kt * 64 + r) * DD + (size_t)h * HDIM;
        const size_t gv = ((size_t)bh * HDIM + r) * SS + kt * 64;
        #pragma unroll
        for (int cc = 0; cc < 2; cc++) {
            const int c = cb + cc * 4;
            const uint32_t sa = s0 + r * FSTR + c * 16;
            CP_ASYNC16(sa + 0 * KVARR, g_kh + gk + c * 8);
            CP_ASYNC16(sa + 1 * KVARR, g_kl + gk + c * 8);
            CP_ASYNC16(sa + 2 * KVARR, g_vth + gv + c * 8);
            CP_ASYNC16(sa + 3 * KVARR, g_vtl + gv + c * 8);
        }
        CP_COMMIT();
    };

    const int nt = 2 * qt + 2;
    load_kv(0, 0);

    const int b_r = (lane & 7) + ((lane >> 4) << 3);
    const int b_c = (lane >> 3) & 1;
    const int r0loc = warp * 16 + (lane >> 2);
    const float scale = 0.125f;

    for (int kt = 0; kt < nt; kt++) {
        CP_WAIT0();
        __syncthreads();
        if (kt + 1 < nt) load_kv(kt + 1, (kt + 1) & 1);

        const uint32_t s0 = sb + (kt & 1) * KVSTAGE;

        float sacc[8][4];
        #pragma unroll
        for (int i = 0; i < 8; i++)
            #pragma unroll
            for (int j = 0; j < 4; j++) sacc[i][j] = 0.f;

        #pragma unroll
        for (int ks = 0; ks < 4; ks++) {
            uint32_t kfh[8][2], kfl[8][2];
            #pragma unroll
            for (int nb = 0; nb < 4; nb++) {
                uint32_t addr = s0 + (nb * 16 + b_r) * FSTR + (ks * 2 + b_c) * 16;
                uint32_t t0, t1, t2, t3;
                LDSM4(t0, t1, t2, t3, addr);
                kfh[2 * nb][0] = t0; kfh[2 * nb][1] = t1;
                kfh[2 * nb + 1][0] = t2; kfh[2 * nb + 1][1] = t3;
                LDSM4(t0, t1, t2, t3, addr + KVARR);
                kfl[2 * nb][0] = t0; kfl[2 * nb][1] = t1;
                kfl[2 * nb + 1][0] = t2; kfl[2 * nb + 1][1] = t3;
            }
            #pragma unroll
            for (int nb = 0; nb < 8; nb++) {
                MMA16816(sacc[nb], qf[0][ks], kfh[nb]);
                MMA16816(sacc[nb], qf[0][ks], kfl[nb]);
                MMA16816(sacc[nb], qf[1][ks], kfh[nb]);
            }
        }

        const bool diag = (kt >= 2 * qt);
        #pragma unroll
        for (int nb = 0; nb < 8; nb++)
            #pragma unroll
            for (int e = 0; e < 4; e++) {
                float s = sacc[nb][e] * scale;
                if (diag) {
                    int row = qbase + r0loc + ((e >= 2) ? 8 : 0);
                    int col = kt * 64 + nb * 8 + (lane & 3) * 2 + (e & 1);
                    if (col > row) s = -3.0e38f;
                }
                sacc[nb][e] = s;
            }

        float rm[2] = {-3.0e38f, -3.0e38f};
        #pragma unroll
        for (int nb = 0; nb < 8; nb++) {
            rm[0] = fmaxf(rm[0], fmaxf(sacc[nb][0], sacc[nb][1]));
            rm[1] = fmaxf(rm[1], fmaxf(sacc[nb][2], sacc[nb][3]));
        }
        #pragma unroll
        for (int j = 0; j < 2; j++) {
            rm[j] = fmaxf(rm[j], __shfl_xor_sync(0xffffffffu, rm[j], 1));
            rm[j] = fmaxf(rm[j], __shfl_xor_sync(0xffffffffu, rm[j], 2));
        }
        float alpha[2];
        #pragma unroll
        for (int j = 0; j < 2; j++) {
            float mn = fmaxf(mi[j], rm[j]);
            alpha[j] = __expf(mi[j] - mn);
            mi[j] = mn;
        }
        float rs[2] = {0.f, 0.f};
        #pragma unroll
        for (int nb = 0; nb < 8; nb++) {
            float p0 = __expf(sacc[nb][0] - mi[0]);
            float p1 = __expf(sacc[nb][1] - mi[0]);
            float p2 = __expf(sacc[nb][2] - mi[1]);
            float p3 = __expf(sacc[nb][3] - mi[1]);
            sacc[nb][0] = p0; sacc[nb][1] = p1;
            sacc[nb][2] = p2; sacc[nb][3] = p3;
            rs[0] += p0 + p1;
            rs[1] += p2 + p3;
        }
        #pragma unroll
        for (int j = 0; j < 2; j++) {
            rs[j] += __shfl_xor_sync(0xffffffffu, rs[j], 1);
            rs[j] += __shfl_xor_sync(0xffffffffu, rs[j], 2);
            li[j] = li[j] * alpha[j] + rs[j];
        }
        #pragma unroll
        for (int nb = 0; nb < 8; nb++) {
            oacc[nb][0] *= alpha[0]; oacc[nb][1] *= alpha[0];
            oacc[nb][2] *= alpha[1]; oacc[nb][3] *= alpha[1];
        }

        uint32_t pf[2][4][4];
        #pragma unroll
        for (int ks = 0; ks < 4; ks++) {
            split_pack2(sacc[2 * ks][0],     sacc[2 * ks][1],     pf[0][ks][0], pf[1][ks][0]);
            split_pack2(sacc[2 * ks][2],     sacc[2 * ks][3],     pf[0][ks][1], pf[1][ks][1]);
            split_pack2(sacc[2 * ks + 1][0], sacc[2 * ks + 1][1], pf[0][ks][2], pf[1][ks][2]);
            split_pack2(sacc[2 * ks + 1][2], sacc[2 * ks + 1][3], pf[0][ks][3], pf[1][ks][3]);
        }

        #pragma unroll
        for (int ks = 0; ks < 4; ks++) {
            uint32_t vfh[8][2], vfl[8][2];
            #pragma unroll
            for (int nb = 0; nb < 4; nb++) {
                uint32_t addr = s0 + 2 * KVARR + (nb * 16 + b_r) * FSTR + (ks * 2 + b_c) * 16;
                uint32_t t0, t1, t2, t3;
                LDSM4(t0, t1, t2, t3, addr);
                vfh[2 * nb][0] = t0; vfh[2 * nb][1] = t1;
                vfh[2 * nb + 1][0] = t2; vfh[2 * nb + 1][1] = t3;
                LDSM4(t0, t1, t2, t3, addr + KVARR);
                vfl[2 * nb][0] = t0; vfl[2 * nb][1] = t1;
                vfl[2 * nb + 1][0] = t2; vfl[2 * nb + 1][1] = t3;
            }
            #pragma unroll
            for (int nb = 0; nb < 8; nb++) {
                MMA16816(oacc[nb], pf[0][ks], vfh[nb]);
                MMA16816(oacc[nb], pf[0][ks], vfl[nb]);
                MMA16816(oacc[nb], pf[1][ks], vfh[nb]);
            }
        }
    }

    const float inv0 = 1.f / li[0];
    const float inv1 = 1.f / li[1];
    const size_t m0 = mbase + qbase + r0loc;
    #pragma unroll
    for (int nb = 0; nb < 8; nb++) {
        const int col = h * HDIM + nb * 8 + (lane & 3) * 2;
        uint32_t hi, lo;
        split_pack2(oacc[nb][0] * inv0, oacc[nb][1] * inv0, hi, lo);
        *(uint32_t*)(g_aoh + m0 * DD + col) = hi;
        *(uint32_t*)(g_aol + m0 * DD + col) = lo;
        split_pack2(oacc[nb][2] * inv1, oacc[nb][3] * inv1, hi, lo);
        *(uint32_t*)(g_aoh + (m0 + 8) * DD + col) = hi;
        *(uint32_t*)(g_aol + (m0 + 8) * DD + col) = lo;
    }
}

// ---------------------------------------------------------------------------
// kernel_launch
// ---------------------------------------------------------------------------
extern "C" void kernel_launch(void* const* d_in, const int* in_sizes, int n_in,
                              void* d_out, int out_size) {
    const float* x  = (const float*)d_in[0];
    float* out = (float*)d_out;

    __nv_bfloat16 *xh, *xl, *aoh, *aol, *wth, *wtl;
    cudaGetSymbolAddress((void**)&xh,  g_xh);
    cudaGetSymbolAddress((void**)&xl,  g_xl);
    cudaGetSymbolAddress((void**)&aoh, g_aoh);
    cudaGetSymbolAddress((void**)&aol, g_aol);
    cudaGetSymbolAddress((void**)&wth, g_wth);
    cudaGetSymbolAddress((void**)&wtl, g_wtl);

    cudaFuncSetAttribute(gemm_qkv, cudaFuncAttributeMaxDynamicSharedMemorySize,
                         SMEM_GEMM);
    cudaFuncSetAttribute(gemm_one, cudaFuncAttributeMaxDynamicSharedMemorySize,
                         SMEM_GEMM);
    cudaFuncSetAttribute(flash_tc, cudaFuncAttributeMaxDynamicSharedMemorySize,
                         SMEM_FLASH);

    // Fused prep: weight transpose+split AND activation split, one launch
    prep_kernel<<<8192, 256>>>(x, (const float*)d_in[2], (const float*)d_in[3],
                               (const float*)d_in[4], (const float*)d_in[5]);

    // QKV projections (bf16x3 HMMA)
    gemm_qkv<<<dim3(24, 32), 256, SMEM_GEMM>>>(xh, xl, wth, wtl);

    // Fused mid: RoPE+split Q/K AND V transpose+split, one launch
    mid_kernel<<<12288, 256>>>();

    // Flash attention (writes split ao directly)
    flash_tc<<<dim3(NQT, BB * HH), 256, SMEM_FLASH>>>();

    // Output projection
    gemm_one<<<dim3(8, 32), 256, SMEM_GEMM>>>(aoh, aol, wth + 3 * (size_t)DD * DD,
                                              wtl + 3 * (size_t)DD * DD, out);
}